// round 7
// baseline (speedup 1.0000x reference)
#include <cuda_runtime.h>

// PIF integrate-and-fire, closed form:
//   spikes = clamp(floor(x + 0.5f), 0, 8)   (bit-exact vs the T=8 scan:
//   v0 = x + 0.5, v at step t is exactly v0 - t in fp32 over the relevant
//   range, so spike count = #{t in [0,8): v0 - t >= 1} = clamp(floor(v0),0,8))
//
// HBM-bound streaming pass: 205.5 MB in + 205.5 MB out (irreducible).
// Measured roofline: ~6.2 TB/s for the 50/50 R/W mix, invariant across
// MLP∈{1,4,8}, occ∈{49%,79%}, .cs/.cg (R1-R6).
//
// R7: persistent one-wave grid-stride variant (1184 blocks = 148 SMs x 8).
// Removes ~10 wave transitions and keeps load queues continuously primed.
// Prediction: neutral to -1us; falsification run for the wave-overhead term.

#define TPB 256
#define VPT 4                      // float4s per thread
#define TILE (TPB * VPT)           // float4s per block-tile = 1024
#define PERSIST_BLOCKS (148 * 8)   // one full wave at occ 8

__device__ __forceinline__ float4 pif4(float4 v) {
    float4 r;
    r.x = fminf(fmaxf(floorf(v.x + 0.5f), 0.0f), 8.0f);
    r.y = fminf(fmaxf(floorf(v.y + 0.5f), 0.0f), 8.0f);
    r.z = fminf(fmaxf(floorf(v.z + 0.5f), 0.0f), 8.0f);
    r.w = fminf(fmaxf(floorf(v.w + 0.5f), 0.0f), 8.0f);
    return r;
}

// Grid-stride over full tiles; zero per-access predication inside a tile.
__global__ void __launch_bounds__(TPB) pif_persist(const float4* __restrict__ x,
                                                   float4* __restrict__ out,
                                                   int n_tiles) {
    for (int tile = blockIdx.x; tile < n_tiles; tile += gridDim.x) {
        int base = tile * TILE + threadIdx.x;
        float4 v[VPT];
        #pragma unroll
        for (int k = 0; k < VPT; k++)      // 4 independent LDG.128 (evict-first)
            v[k] = __ldcs(x + base + k * TPB);
        #pragma unroll
        for (int k = 0; k < VPT; k++)
            __stcs(out + base + k * TPB, pif4(v[k]));
    }
}

// Ragged edge (float4 granularity) — not hit for this shape, kept for safety.
__global__ void pif_edge4(const float4* __restrict__ x, float4* __restrict__ out,
                          int start, int n4) {
    int i = start + blockIdx.x * blockDim.x + threadIdx.x;
    if (i < n4) __stcs(out + i, pif4(__ldcs(x + i)));
}

// Ragged edge (scalar granularity) — not hit for this shape, kept for safety.
__global__ void pif_tail(const float* __restrict__ x, float* __restrict__ out,
                         int start, int n) {
    int i = start + blockIdx.x * blockDim.x + threadIdx.x;
    if (i < n) out[i] = fminf(fmaxf(floorf(x[i] + 0.5f), 0.0f), 8.0f);
}

extern "C" void kernel_launch(void* const* d_in, const int* in_sizes, int n_in,
                              void* d_out, int out_size) {
    const float* x = (const float*)d_in[0];
    float* out = (float*)d_out;
    int n = in_sizes[0];

    int n4 = n / 4;
    int n_tiles = n4 / TILE;
    if (n_tiles > 0) {
        int blocks = n_tiles < PERSIST_BLOCKS ? n_tiles : PERSIST_BLOCKS;
        pif_persist<<<blocks, TPB>>>((const float4*)x, (float4*)out, n_tiles);
    }
    int done4 = n_tiles * TILE;
    if (done4 < n4) {
        int rem = n4 - done4;
        pif_edge4<<<(rem + TPB - 1) / TPB, TPB>>>((const float4*)x, (float4*)out,
                                                  done4, n4);
    }
    int rem_start = n4 * 4;
    if (rem_start < n) {
        int rem = n - rem_start;
        pif_tail<<<(rem + TPB - 1) / TPB, TPB>>>(x, out, rem_start, rem);
    }
}

// round 8
// speedup vs baseline: 1.1563x; 1.1563x over previous
#include <cuda_runtime.h>

// PIF integrate-and-fire, closed form:
//   spikes = clamp(floor(x + 0.5f), 0, 8)   (bit-exact vs the T=8 scan:
//   v0 = x + 0.5, v at step t is exactly v0 - t in fp32 over the relevant
//   range, so spike count = #{t in [0,8): v0 - t >= 1} = clamp(floor(v0),0,8))
//
// HBM-bound streaming pass: 205.5 MB in + 205.5 MB out (irreducible).
// Measured roofline on this chip: ~6.2 TB/s for the 50/50 R/W mix.
// Design space fully mapped (R1-R7):
//   MLP=1:61.9us  MLP=4/.cs:57.7us  MLP=8:58.1us  MLP=4/.cg:58.6us
//   persistent grid-stride:64.1us (loop serializes tile loads -> MLP bubble)
// Final config = measured optimum, reproduced twice: flat grid, MLP=4 @27regs
// (occ ~78%), evict-first .cs both sides, branch-free exact-tile main kernel
// (n4 = 12544 * 1024 exactly -> single launch for this shape).

#define TPB 256
#define VPT 4                      // float4s per thread
#define TILE (TPB * VPT)           // float4s per block = 1024

__device__ __forceinline__ float4 pif4(float4 v) {
    float4 r;
    r.x = fminf(fmaxf(floorf(v.x + 0.5f), 0.0f), 8.0f);
    r.y = fminf(fmaxf(floorf(v.y + 0.5f), 0.0f), 8.0f);
    r.z = fminf(fmaxf(floorf(v.z + 0.5f), 0.0f), 8.0f);
    r.w = fminf(fmaxf(floorf(v.w + 0.5f), 0.0f), 8.0f);
    return r;
}

// Full tiles only — zero predication, compile-time offsets.
__global__ void __launch_bounds__(TPB) pif_main(const float4* __restrict__ x,
                                                float4* __restrict__ out) {
    int base = blockIdx.x * TILE + threadIdx.x;

    float4 v[VPT];
    #pragma unroll
    for (int k = 0; k < VPT; k++)          // 4 independent LDG.128 (evict-first)
        v[k] = __ldcs(x + base + k * TPB);
    #pragma unroll
    for (int k = 0; k < VPT; k++)
        __stcs(out + base + k * TPB, pif4(v[k]));
}

// Ragged edge (float4 granularity) — not hit for this shape, kept for safety.
__global__ void pif_edge4(const float4* __restrict__ x, float4* __restrict__ out,
                          int start, int n4) {
    int i = start + blockIdx.x * blockDim.x + threadIdx.x;
    if (i < n4) __stcs(out + i, pif4(__ldcs(x + i)));
}

// Ragged edge (scalar granularity) — not hit for this shape, kept for safety.
__global__ void pif_tail(const float* __restrict__ x, float* __restrict__ out,
                         int start, int n) {
    int i = start + blockIdx.x * blockDim.x + threadIdx.x;
    if (i < n) out[i] = fminf(fmaxf(floorf(x[i] + 0.5f), 0.0f), 8.0f);
}

extern "C" void kernel_launch(void* const* d_in, const int* in_sizes, int n_in,
                              void* d_out, int out_size) {
    const float* x = (const float*)d_in[0];
    float* out = (float*)d_out;
    int n = in_sizes[0];

    int n4 = n / 4;
    int full_blocks = n4 / TILE;
    if (full_blocks > 0) {
        pif_main<<<full_blocks, TPB>>>((const float4*)x, (float4*)out);
    }
    int done4 = full_blocks * TILE;
    if (done4 < n4) {
        int rem = n4 - done4;
        pif_edge4<<<(rem + TPB - 1) / TPB, TPB>>>((const float4*)x, (float4*)out,
                                                  done4, n4);
    }
    int rem_start = n4 * 4;
    if (rem_start < n) {
        int rem = n - rem_start;
        pif_tail<<<(rem + TPB - 1) / TPB, TPB>>>(x, out, rem_start, rem);
    }
}